// round 11
// baseline (speedup 1.0000x reference)
#include <cuda_runtime.h>
#include <cuda_fp16.h>
#include <cstdint>
#include <cstddef>

// pre-converted fp16 weights, transposed to [n][k]
__device__ __align__(16) __half g_W1h[128 * 256];
__device__ __align__(16) __half g_W2h[64 * 128];

namespace {

constexpr int THREADS = 448;   // 14 warps: 7 M-warps (32 rows) x 2 N-warps (64 cols)
constexpr int BPB     = 16;
constexpr int ROWS    = 224;

constexpr int W1SW = 132;  // W1T full-K stride (words): 128 data + 4 pad  (132%32==4)
constexpr int HSW  = 68;   // Y/H fp16 stride (words)
constexpr int W2SW = 68;   // W2T fp16 stride (words)
constexpr int ZSF  = 72;   // Z f32 stride (floats)

// smem byte offsets
constexpr int O_BIAS = 0;                              // b1(512B)+b2(256B)
constexpr int O_W1   = 1024;                           // 128*132*4 = 67584
constexpr int O_W2   = O_W1 + 128 * W1SW * 4;          // 68608, 64*68*4 = 17408
constexpr int O_UNI  = O_W2 + 64 * W2SW * 4;           // 86016: YH fp16 (60928) | Z f32 (64512)
constexpr int SMEM_BYTES = O_UNI + ROWS * ZSF * 4;     // 150528

__device__ __forceinline__ uint32_t packh2(float a, float b) {
    __half2 h = __floats2half2_rn(a, b);
    return *reinterpret_cast<uint32_t*>(&h);
}

__device__ __forceinline__ void mma16816(float* d,
                                         uint32_t a0, uint32_t a1, uint32_t a2, uint32_t a3,
                                         uint32_t b0, uint32_t b1) {
    asm volatile(
        "mma.sync.aligned.m16n8k16.row.col.f32.f16.f16.f32 "
        "{%0,%1,%2,%3},{%4,%5,%6,%7},{%8,%9},{%0,%1,%2,%3};\n"
        : "+f"(d[0]), "+f"(d[1]), "+f"(d[2]), "+f"(d[3])
        : "r"(a0), "r"(a1), "r"(a2), "r"(a3), "r"(b0), "r"(b1));
}

__device__ __forceinline__ void cp16(uint32_t dst_smem, const void* src) {
    asm volatile("cp.async.cg.shared.global [%0], [%1], 16;\n"
                 :: "r"(dst_smem), "l"(src));
}
__device__ __forceinline__ void cp_commit() {
    asm volatile("cp.async.commit_group;\n" ::: "memory");
}
__device__ __forceinline__ void cp_wait0() {
    asm volatile("cp.async.wait_group 0;\n" ::: "memory");
}

// A_hat: degrees (with self-loop) = 3 at teeth {0,6,7,13}, else 4
constexpr float CA = 0.3333333333333333f;
constexpr float CB = 0.28867513459481287f;
constexpr float CC = 0.25f;

__device__ __forceinline__ float2 m3(float wa, float2 a, float wb, float2 b,
                                     float wc, float2 c) {
    return make_float2(wa * a.x + wb * b.x + wc * c.x,
                       wa * a.y + wb * b.y + wc * c.y);
}
__device__ __forceinline__ float2 m4(float wa, float2 a, float wb, float2 b,
                                     float wc, float2 c, float wd, float2 d) {
    return make_float2(wa * a.x + wb * b.x + wc * c.x + wd * d.x,
                       wa * a.y + wb * b.y + wc * c.y + wd * d.y);
}

__device__ __forceinline__ void ahat14(const float* y, float* o) {
    o[0]  = CA*y[0] + CB*y[1] + CA*y[7];
    o[1]  = CB*y[0] + CC*y[1] + CC*y[2]  + CC*y[8];
    o[2]  = CC*y[1] + CC*y[2] + CC*y[3]  + CC*y[9];
    o[3]  = CC*y[2] + CC*y[3] + CC*y[4]  + CC*y[10];
    o[4]  = CC*y[3] + CC*y[4] + CC*y[5]  + CC*y[11];
    o[5]  = CC*y[4] + CC*y[5] + CB*y[6]  + CC*y[12];
    o[6]  = CB*y[5] + CA*y[6] + CA*y[13];
    o[7]  = CA*y[0] + CA*y[7] + CB*y[8];
    o[8]  = CC*y[1] + CB*y[7] + CC*y[8]  + CC*y[9];
    o[9]  = CC*y[2] + CC*y[8] + CC*y[9]  + CC*y[10];
    o[10] = CC*y[3] + CC*y[9] + CC*y[10] + CC*y[11];
    o[11] = CC*y[4] + CC*y[10]+ CC*y[11] + CC*y[12];
    o[12] = CC*y[5] + CC*y[11]+ CC*y[12] + CB*y[13];
    o[13] = CA*y[6] + CB*y[12]+ CA*y[13];
}

} // namespace

__global__ void prep_kernel(const float* __restrict__ W1, const float* __restrict__ W2) {
    int t = blockIdx.x * 256 + threadIdx.x;
    if (t < 32768) {
        int n = t >> 8, k = t & 255;
        g_W1h[n * 256 + k] = __float2half_rn(W1[k * 128 + n]);
    } else if (t < 40960) {
        int u = t - 32768;
        int n = u >> 7, k = u & 127;
        g_W2h[n * 128 + k] = __float2half_rn(W2[k * 64 + n]);
    }
}

__global__ void __launch_bounds__(THREADS, 1)
gcn_ldg_kernel(const float* __restrict__ fea,
               const float* __restrict__ b1,
               const float* __restrict__ b2,
               float* __restrict__ out)
{
    extern __shared__ char sm[];
    const uint32_t smb = (uint32_t)__cvta_generic_to_shared(sm);

    float*    b1s = (float*)(sm + O_BIAS);
    float*    b2s = (float*)(sm + O_BIAS + 512);
    uint32_t* W1w = (uint32_t*)(sm + O_W1);
    uint32_t* W2w = (uint32_t*)(sm + O_W2);
    uint32_t* YHw = (uint32_t*)(sm + O_UNI);   // [224][68w] fp16
    float*    Zf  = (float*)(sm + O_UNI);      // [224][72]  f32 (aliases YH)

    const int tid  = threadIdx.x;
    const int warp = tid >> 5;
    const int lane = tid & 31;
    const int g    = lane >> 2;
    const int t    = lane & 3;
    const int wm   = warp >> 1;   // 0..6: 32-row M tile
    const int wn   = warp & 1;    // 0..1: 64-col N tile
    const int blk  = blockIdx.x;

    const float* feaB = fea + (size_t)blk * ROWS * 256;

    // ---------------- prologue: stage full W1T + W2T, biases ----------------
    if (tid < 128) b1s[tid] = b1[tid];
    else if (tid < 192) b2s[tid - 128] = b2[tid - 128];

    // W1T: 128 rows x 256 halves = 4096 x 16B
    for (int i = tid; i < 4096; i += THREADS) {
        int n = i >> 5, q = i & 31;
        cp16(smb + O_W1 + (uint32_t)(n * W1SW + q * 4) * 4,
             g_W1h + n * 256 + q * 8);
    }
    // W2T: 64 rows x 128 halves = 1024 x 16B
    for (int i = tid; i < 1024; i += THREADS) {
        int n = i >> 4, q = i & 15;
        cp16(smb + O_W2 + (uint32_t)(n * W2SW + q * 4) * 4,
             g_W2h + n * 128 + q * 8);
    }
    cp_commit();
    cp_wait0();
    __syncthreads();

    // ---------------- GEMM1: Y[224,128] = X * W1T^T, K=256, sync-free ----------------
    // A fragments read directly from global: thread (g,t), tile row base r0=wm*32.
    // a0 = X[r0+g][16st+2t..+1], a1 = +8 rows, a2 = +8 cols, a3 = both.
    float acc1[2][8][4];
    #pragma unroll
    for (int mt = 0; mt < 2; ++mt)
        #pragma unroll
        for (int nt = 0; nt < 8; ++nt)
            #pragma unroll
            for (int r = 0; r < 4; ++r) acc1[mt][nt][r] = 0.f;

    const float* xp00 = feaB + (wm * 32 + g) * 256 + 2 * t;        // mt0, a0 base
    const uint32_t* bbase = W1w + (wn * 64 + g) * W1SW + t;

    float2 pv[8];
    // preload step 0
    #pragma unroll
    for (int mt = 0; mt < 2; ++mt) {
        const float* p = xp00 + mt * 16 * 256;
        pv[mt * 4 + 0] = *(const float2*)(p);
        pv[mt * 4 + 1] = *(const float2*)(p + 8 * 256);
        pv[mt * 4 + 2] = *(const float2*)(p + 8);
        pv[mt * 4 + 3] = *(const float2*)(p + 8 * 256 + 8);
    }

    #pragma unroll
    for (int st = 0; st < 16; ++st) {
        float2 nv[8];
        if (st < 15) {
            #pragma unroll
            for (int mt = 0; mt < 2; ++mt) {
                const float* p = xp00 + mt * 16 * 256 + (st + 1) * 16;
                nv[mt * 4 + 0] = *(const float2*)(p);
                nv[mt * 4 + 1] = *(const float2*)(p + 8 * 256);
                nv[mt * 4 + 2] = *(const float2*)(p + 8);
                nv[mt * 4 + 3] = *(const float2*)(p + 8 * 256 + 8);
            }
        }
        uint32_t a[2][4];
        #pragma unroll
        for (int mt = 0; mt < 2; ++mt)
            #pragma unroll
            for (int r = 0; r < 4; ++r)
                a[mt][r] = packh2(pv[mt * 4 + r].x, pv[mt * 4 + r].y);

        const uint32_t* bp0 = bbase + st * 8;
        #pragma unroll
        for (int nt = 0; nt < 8; ++nt) {
            const uint32_t* bp = bp0 + nt * 8 * W1SW;
            uint32_t b0 = bp[0], b1v = bp[4];
            mma16816(acc1[0][nt], a[0][0], a[0][1], a[0][2], a[0][3], b0, b1v);
            mma16816(acc1[1][nt], a[1][0], a[1][1], a[1][2], a[1][3], b0, b1v);
        }
        #pragma unroll
        for (int j = 0; j < 8; ++j) pv[j] = nv[j];
    }

    // ---------------- Y -> YH (fp16) ----------------
    #pragma unroll
    for (int mt = 0; mt < 2; ++mt) {
        int r0 = wm * 32 + mt * 16 + g;
        __half2* h0 = (__half2*)YHw + r0 * HSW + wn * 32 + t;
        __half2* h1 = h0 + 8 * HSW;
        #pragma unroll
        for (int nt = 0; nt < 8; ++nt) {
            h0[nt * 4] = __floats2half2_rn(acc1[mt][nt][0], acc1[mt][nt][1]);
            h1[nt * 4] = __floats2half2_rn(acc1[mt][nt][2], acc1[mt][nt][3]);
        }
    }
    __syncthreads();

    // ---------------- A_hat pass 1 (+b1, relu), in place on fp16 YH ----------------
    const float2* b1s2 = (const float2*)b1s;
    for (int task = tid; task < BPB * 64; task += THREADS) {
        int b = task >> 6, cw = task & 63;
        __half2* p = (__half2*)YHw + (b * 14) * HSW + cw;
        float2 y[14];
        #pragma unroll
        for (int i = 0; i < 14; ++i) y[i] = __half22float2(p[i * HSW]);
        float2 bias = b1s2[cw];
        float2 o[14];
        o[0]  = m3(CA,y[0], CB,y[1], CA,y[7]);
        o[1]  = m4(CB,y[0], CC,y[1], CC,y[2],  CC,y[8]);
        o[2]  = m4(CC,y[1], CC,y[2], CC,y[3],  CC,y[9]);
        o[3]  = m4(CC,y[2], CC,y[3], CC,y[4],  CC,y[10]);
        o[4]  = m4(CC,y[3], CC,y[4], CC,y[5],  CC,y[11]);
        o[5]  = m4(CC,y[4], CC,y[5], CB,y[6],  CC,y[12]);
        o[6]  = m3(CB,y[5], CA,y[6], CA,y[13]);
        o[7]  = m3(CA,y[0], CA,y[7], CB,y[8]);
        o[8]  = m4(CC,y[1], CB,y[7], CC,y[8],  CC,y[9]);
        o[9]  = m4(CC,y[2], CC,y[8], CC,y[9],  CC,y[10]);
        o[10] = m4(CC,y[3], CC,y[9], CC,y[10], CC,y[11]);
        o[11] = m4(CC,y[4], CC,y[10],CC,y[11], CC,y[12]);
        o[12] = m4(CC,y[5], CC,y[11],CC,y[12], CB,y[13]);
        o[13] = m3(CA,y[6], CB,y[12],CA,y[13]);
        #pragma unroll
        for (int i = 0; i < 14; ++i) {
            p[i * HSW] = __floats2half2_rn(fmaxf(o[i].x + bias.x, 0.f),
                                           fmaxf(o[i].y + bias.y, 0.f));
        }
    }
    __syncthreads();

    // ---------------- GEMM2: Z[224,64] = H * W2T^T, K=128 ----------------
    float acc2[2][4][4];
    #pragma unroll
    for (int mt = 0; mt < 2; ++mt)
        #pragma unroll
        for (int nt = 0; nt < 4; ++nt)
            #pragma unroll
            for (int r = 0; r < 4; ++r) acc2[mt][nt][r] = 0.f;

    #pragma unroll
    for (int s = 0; s < 8; ++s) {
        uint32_t a[2][4];
        #pragma unroll
        for (int mt = 0; mt < 2; ++mt) {
            const uint32_t* ap = YHw + (wm * 32 + mt * 16 + g) * HSW + s * 8 + t;
            a[mt][0] = ap[0];
            a[mt][1] = ap[8 * HSW];
            a[mt][2] = ap[4];
            a[mt][3] = ap[8 * HSW + 4];
        }
        const uint32_t* bp0 = W2w + (wn * 32 + g) * W2SW + s * 8 + t;
        #pragma unroll
        for (int nt = 0; nt < 4; ++nt) {
            const uint32_t* bp = bp0 + nt * 8 * W2SW;
            uint32_t b0 = bp[0], b1v = bp[4];
            mma16816(acc2[0][nt], a[0][0], a[0][1], a[0][2], a[0][3], b0, b1v);
            mma16816(acc2[1][nt], a[1][0], a[1][1], a[1][2], a[1][3], b0, b1v);
        }
    }
    __syncthreads();   // all YH reads done before Z overwrites the region

    // ---------------- Z -> smem (f32) ----------------
    #pragma unroll
    for (int mt = 0; mt < 2; ++mt) {
        int r0 = wm * 32 + mt * 16 + g;
        float* z0 = Zf + r0 * ZSF + wn * 32 + 2 * t;
        float* z1 = z0 + 8 * ZSF;
        #pragma unroll
        for (int nt = 0; nt < 4; ++nt) {
            *(float2*)(z0 + nt * 8) = make_float2(acc2[mt][nt][0], acc2[mt][nt][1]);
            *(float2*)(z1 + nt * 8) = make_float2(acc2[mt][nt][2], acc2[mt][nt][3]);
        }
    }
    __syncthreads();

    // ---------------- A_hat pass 2 (+b2) -> global ----------------
    float* gout = out + (size_t)blk * ROWS * 64;
    for (int task = tid; task < BPB * 64; task += THREADS) {
        int b = task >> 6, col = task & 63;
        const float* zp = Zf + b * 14 * ZSF + col;
        float z[14], o[14];
        #pragma unroll
        for (int i = 0; i < 14; ++i) z[i] = zp[i * ZSF];
        ahat14(z, o);
        float bv = b2s[col];
        float* gp = gout + (b * 14) * 64 + col;
        #pragma unroll
        for (int i = 0; i < 14; ++i) gp[i * 64] = o[i] + bv;
    }
}

extern "C" void kernel_launch(void* const* d_in, const int* in_sizes, int n_in,
                              void* d_out, int out_size) {
    const float* fea = (const float*)d_in[0];
    const float* W1  = (const float*)d_in[1];
    const float* b1  = (const float*)d_in[2];
    const float* W2  = (const float*)d_in[3];
    const float* b2  = (const float*)d_in[4];
    float* out = (float*)d_out;

    int B = in_sizes[0] / (14 * 256);   // 16384
    int blocks = B / BPB;               // 1024

    prep_kernel<<<160, 256>>>(W1, W2);
    cudaFuncSetAttribute(gcn_ldg_kernel,
                         cudaFuncAttributeMaxDynamicSharedMemorySize, SMEM_BYTES);
    gcn_ldg_kernel<<<blocks, THREADS, SMEM_BYTES>>>(fea, b1, b2, out);
}

// round 13
// speedup vs baseline: 1.2263x; 1.2263x over previous
#include <cuda_runtime.h>
#include <cuda_fp16.h>
#include <cstdint>
#include <cstddef>

// pre-converted fp16 weights, transposed to [n][k]
__device__ __align__(16) __half g_W1h[128 * 256];
__device__ __align__(16) __half g_W2h[64 * 128];

namespace {

constexpr int THREADS = 256;   // 8 warps: 4 M-warps (32 rows) x 2 N-warps (64 cols)
constexpr int BPB     = 8;
constexpr int ROWS    = 112;   // real rows; M padded to 128
constexpr int MPAD    = 128;

constexpr int XSW  = 20;   // X fp16 chunk stride (words)
constexpr int WSW  = 20;   // W1 fp16 chunk stride
constexpr int HSW  = 68;   // Y/H fp16 stride (words)
constexpr int W2SW = 68;   // W2T fp16 stride
constexpr int ZSF  = 72;   // Z f32 stride (floats)

constexpr int XBUFW = MPAD * XSW;   // 2560 words per X buffer
constexpr int WBUFW = 128 * WSW;    // 2560 words per W1 buffer

// byte offsets; union region holds {X+W1 staging | YH fp16 | Z f32}
constexpr int O_BIAS = 0;                       // b1(512B)+b2(256B)
constexpr int O_X    = 1024;                    // 2*2560*4 = 20480
constexpr int O_W1   = O_X + 2 * XBUFW * 4;     // 21504, 2*2560*4 = 20480
constexpr int UNION  = 40960;                   // staging 40960 | YH 34816 | Z 36864
constexpr int O_W2   = O_X + UNION;             // 41984
constexpr int SMEM_BYTES = O_W2 + 64 * W2SW * 4;  // 59392

__device__ __forceinline__ uint32_t packh2(float a, float b) {
    __half2 h = __floats2half2_rn(a, b);
    return *reinterpret_cast<uint32_t*>(&h);
}

__device__ __forceinline__ void mma16816(float* d,
                                         uint32_t a0, uint32_t a1, uint32_t a2, uint32_t a3,
                                         uint32_t b0, uint32_t b1) {
    asm volatile(
        "mma.sync.aligned.m16n8k16.row.col.f32.f16.f16.f32 "
        "{%0,%1,%2,%3},{%4,%5,%6,%7},{%8,%9},{%0,%1,%2,%3};\n"
        : "+f"(d[0]), "+f"(d[1]), "+f"(d[2]), "+f"(d[3])
        : "r"(a0), "r"(a1), "r"(a2), "r"(a3), "r"(b0), "r"(b1));
}

__device__ __forceinline__ void cp16(uint32_t dst_smem, const void* src) {
    asm volatile("cp.async.cg.shared.global [%0], [%1], 16;\n"
                 :: "r"(dst_smem), "l"(src));
}
__device__ __forceinline__ void cp_commit() {
    asm volatile("cp.async.commit_group;\n" ::: "memory");
}
__device__ __forceinline__ void cp_wait0() {
    asm volatile("cp.async.wait_group 0;\n" ::: "memory");
}

// A_hat: degrees (with self-loop) = 3 at teeth {0,6,7,13}, else 4
constexpr float CA = 0.3333333333333333f;
constexpr float CB = 0.28867513459481287f;
constexpr float CC = 0.25f;

__device__ __forceinline__ float2 m3(float wa, float2 a, float wb, float2 b,
                                     float wc, float2 c) {
    return make_float2(wa * a.x + wb * b.x + wc * c.x,
                       wa * a.y + wb * b.y + wc * c.y);
}
__device__ __forceinline__ float2 m4(float wa, float2 a, float wb, float2 b,
                                     float wc, float2 c, float wd, float2 d) {
    return make_float2(wa * a.x + wb * b.x + wc * c.x + wd * d.x,
                       wa * a.y + wb * b.y + wc * c.y + wd * d.y);
}

__device__ __forceinline__ void ahat14(const float* y, float* o) {
    o[0]  = CA*y[0] + CB*y[1] + CA*y[7];
    o[1]  = CB*y[0] + CC*y[1] + CC*y[2]  + CC*y[8];
    o[2]  = CC*y[1] + CC*y[2] + CC*y[3]  + CC*y[9];
    o[3]  = CC*y[2] + CC*y[3] + CC*y[4]  + CC*y[10];
    o[4]  = CC*y[3] + CC*y[4] + CC*y[5]  + CC*y[11];
    o[5]  = CC*y[4] + CC*y[5] + CB*y[6]  + CC*y[12];
    o[6]  = CB*y[5] + CA*y[6] + CA*y[13];
    o[7]  = CA*y[0] + CA*y[7] + CB*y[8];
    o[8]  = CC*y[1] + CB*y[7] + CC*y[8]  + CC*y[9];
    o[9]  = CC*y[2] + CC*y[8] + CC*y[9]  + CC*y[10];
    o[10] = CC*y[3] + CC*y[9] + CC*y[10] + CC*y[11];
    o[11] = CC*y[4] + CC*y[10]+ CC*y[11] + CC*y[12];
    o[12] = CC*y[5] + CC*y[11]+ CC*y[12] + CB*y[13];
    o[13] = CA*y[6] + CB*y[12]+ CA*y[13];
}

} // namespace

__global__ void prep_kernel(const float* __restrict__ W1, const float* __restrict__ W2) {
    int t = blockIdx.x * 256 + threadIdx.x;
    if (t < 32768) {
        int n = t >> 8, k = t & 255;
        g_W1h[n * 256 + k] = __float2half_rn(W1[k * 128 + n]);
    } else if (t < 40960) {
        int u = t - 32768;
        int n = u >> 7, k = u & 127;
        g_W2h[n * 128 + k] = __float2half_rn(W2[k * 64 + n]);
    }
}

__global__ void __launch_bounds__(THREADS, 2)
gcn_occ2_kernel(const float* __restrict__ fea,
                const float* __restrict__ b1,
                const float* __restrict__ b2,
                float* __restrict__ out)
{
    extern __shared__ char sm[];
    const uint32_t smb = (uint32_t)__cvta_generic_to_shared(sm);

    float*    b1s = (float*)(sm + O_BIAS);
    float*    b2s = (float*)(sm + O_BIAS + 512);
    uint32_t* Xw  = (uint32_t*)(sm + O_X);
    uint32_t* W1w = (uint32_t*)(sm + O_W1);
    uint32_t* YHw = (uint32_t*)(sm + O_X);     // [128][68w] fp16, aliases staging
    float*    Zf  = (float*)(sm + O_X);        // [128][72]  f32,  aliases staging
    uint32_t* W2w = (uint32_t*)(sm + O_W2);

    const int tid  = threadIdx.x;
    const int warp = tid >> 5;
    const int lane = tid & 31;
    const int g    = lane >> 2;
    const int t    = lane & 3;
    const int wm   = warp >> 1;   // 0..3: 32-row M tile
    const int wn   = warp & 1;    // 0..1: 64-col N tile
    const int blk  = blockIdx.x;

    const float* feaB = fea + (size_t)blk * ROWS * 256;

    // X staging map: 448 uint4 per chunk (112 rows x 4 segs), <=2 per thread
    const int xrow0 = tid >> 2, xseg0 = tid & 3;         // idx = tid (always < 448)
    const int idx1  = tid + 256;
    const int xrow1 = idx1 >> 2, xseg1 = idx1 & 3;
    const bool has1 = idx1 < 448;

    // ---------------- prologue ----------------
    if (tid < 128) b1s[tid] = b1[tid];
    else if (tid < 192) b2s[tid - 128] = b2[tid - 128];

    // zero pad rows 112..127 of BOTH X buffers (so pad Y rows are exact zeros)
    for (int i = tid; i < 2 * 16 * XSW; i += THREADS) {
        int buf = i / (16 * XSW), r = (i / XSW) % 16, w = i % XSW;
        Xw[buf * XBUFW + (112 + r) * XSW + w] = 0u;
    }

    // W2T (64 x 128 halves = 1024 x 16B)
    for (int i = tid; i < 1024; i += THREADS) {
        int n = i >> 4, seg = i & 15;
        cp16(smb + O_W2 + (uint32_t)(n * W2SW + seg * 4) * 4,
             g_W2h + n * 128 + seg * 8);
    }
    // W1 chunk 0 (128 x 32 halves = 512 x 16B, 2 per thread)
    #pragma unroll
    for (int j = 0; j < 2; ++j) {
        int i = tid + j * THREADS;
        int n = i >> 2, seg = i & 3;
        cp16(smb + O_W1 + (uint32_t)(n * WSW + seg * 4) * 4,
             g_W1h + n * 256 + seg * 8);
    }
    cp_commit();

    // X chunk 0
    {
        const float* xp = feaB + xrow0 * 256 + xseg0 * 8;
        float4 v0 = *(const float4*)xp;
        float4 v1 = *(const float4*)(xp + 4);
        *(uint4*)(Xw + xrow0 * XSW + xseg0 * 4) =
            make_uint4(packh2(v0.x, v0.y), packh2(v0.z, v0.w),
                       packh2(v1.x, v1.y), packh2(v1.z, v1.w));
        if (has1) {
            const float* xq = feaB + xrow1 * 256 + xseg1 * 8;
            float4 w0 = *(const float4*)xq;
            float4 w1 = *(const float4*)(xq + 4);
            *(uint4*)(Xw + xrow1 * XSW + xseg1 * 4) =
                make_uint4(packh2(w0.x, w0.y), packh2(w0.z, w0.w),
                           packh2(w1.x, w1.y), packh2(w1.z, w1.w));
        }
    }
    cp_wait0();
    __syncthreads();

    // ---------------- GEMM1: Y[128,128] = Xpad * W1T^T, K=256 ----------------
    float acc1[2][8][4];
    #pragma unroll
    for (int mt = 0; mt < 2; ++mt)
        #pragma unroll
        for (int nt = 0; nt < 8; ++nt)
            #pragma unroll
            for (int r = 0; r < 4; ++r) acc1[mt][nt][r] = 0.f;

    #pragma unroll 1
    for (int c = 0; c < 8; ++c) {
        float4 pv0[2], pv1[2];
        if (c < 7) {
            int k0 = (c + 1) * 32;
            const float* xp = feaB + xrow0 * 256 + k0 + xseg0 * 8;
            pv0[0] = *(const float4*)xp;
            pv0[1] = *(const float4*)(xp + 4);
            if (has1) {
                const float* xq = feaB + xrow1 * 256 + k0 + xseg1 * 8;
                pv1[0] = *(const float4*)xq;
                pv1[1] = *(const float4*)(xq + 4);
            }
            uint32_t wdst = smb + O_W1 + (uint32_t)(((c + 1) & 1) * WBUFW) * 4;
            #pragma unroll
            for (int j = 0; j < 2; ++j) {
                int i = tid + j * THREADS;
                int n = i >> 2, seg = i & 3;
                cp16(wdst + (uint32_t)(n * WSW + seg * 4) * 4,
                     g_W1h + n * 256 + k0 + seg * 8);
            }
            cp_commit();
        }

        const uint32_t* xb = Xw + (c & 1) * XBUFW;
        const uint32_t* wb = W1w + (c & 1) * WBUFW;
        #pragma unroll
        for (int s = 0; s < 2; ++s) {
            uint32_t a[2][4];
            #pragma unroll
            for (int mt = 0; mt < 2; ++mt) {
                const uint32_t* ap = xb + (wm * 32 + mt * 16 + g) * XSW + s * 8 + t;
                a[mt][0] = ap[0];
                a[mt][1] = ap[8 * XSW];
                a[mt][2] = ap[4];
                a[mt][3] = ap[8 * XSW + 4];
            }
            const uint32_t* bp0 = wb + (wn * 64 + g) * WSW + s * 8 + t;
            #pragma unroll
            for (int nt = 0; nt < 8; ++nt) {
                const uint32_t* bp = bp0 + nt * 8 * WSW;
                uint32_t b0 = bp[0], b1v = bp[4];
                mma16816(acc1[0][nt], a[0][0], a[0][1], a[0][2], a[0][3], b0, b1v);
                mma16816(acc1[1][nt], a[1][0], a[1][1], a[1][2], a[1][3], b0, b1v);
            }
        }

        if (c < 7) {
            uint32_t* xw = Xw + ((c + 1) & 1) * XBUFW;
            *(uint4*)(xw + xrow0 * XSW + xseg0 * 4) =
                make_uint4(packh2(pv0[0].x, pv0[0].y), packh2(pv0[0].z, pv0[0].w),
                           packh2(pv0[1].x, pv0[1].y), packh2(pv0[1].z, pv0[1].w));
            if (has1) {
                *(uint4*)(xw + xrow1 * XSW + xseg1 * 4) =
                    make_uint4(packh2(pv1[0].x, pv1[0].y), packh2(pv1[0].z, pv1[0].w),
                               packh2(pv1[1].x, pv1[1].y), packh2(pv1[1].z, pv1[1].w));
            }
            cp_wait0();
        }
        __syncthreads();
    }

    // ---------------- Y -> YH (fp16, aliases staging; GEMM1 done+synced) ----------------
    #pragma unroll
    for (int mt = 0; mt < 2; ++mt) {
        int r0 = wm * 32 + mt * 16 + g;
        __half2* h0 = (__half2*)YHw + r0 * HSW + wn * 32 + t;
        __half2* h1 = h0 + 8 * HSW;
        #pragma unroll
        for (int nt = 0; nt < 8; ++nt) {
            h0[nt * 4] = __floats2half2_rn(acc1[mt][nt][0], acc1[mt][nt][1]);
            h1[nt * 4] = __floats2half2_rn(acc1[mt][nt][2], acc1[mt][nt][3]);
        }
    }
    __syncthreads();

    // ---------------- A_hat pass 1 (+b1, relu), in place on fp16 YH ----------------
    const float2* b1s2 = (const float2*)b1s;
    #pragma unroll
    for (int task = tid; task < BPB * 64; task += THREADS) {
        int b = task >> 6, cw = task & 63;
        __half2* p = (__half2*)YHw + (b * 14) * HSW + cw;
        float2 y[14];
        #pragma unroll
        for (int i = 0; i < 14; ++i) y[i] = __half22float2(p[i * HSW]);
        float2 bias = b1s2[cw];
        float2 o[14];
        o[0]  = m3(CA,y[0], CB,y[1], CA,y[7]);
        o[1]  = m4(CB,y[0], CC,y[1], CC,y[2],  CC,y[8]);
        o[2]  = m4(CC,y[1], CC,y[2], CC,y[3],  CC,y[9]);
        o[3]  = m4(CC,y[2], CC,y[3], CC,y[4],  CC,y[10]);
        o[4]  = m4(CC,y[3], CC,y[4], CC,y[5],  CC,y[11]);
        o[5]  = m4(CC,y[4], CC,y[5], CB,y[6],  CC,y[12]);
        o[6]  = m3(CB,y[5], CA,y[6], CA,y[13]);
        o[7]  = m3(CA,y[0], CA,y[7], CB,y[8]);
        o[8]  = m4(CC,y[1], CB,y[7], CC,y[8],  CC,y[9]);
        o[9]  = m4(CC,y[2], CC,y[8], CC,y[9],  CC,y[10]);
        o[10] = m4(CC,y[3], CC,y[9], CC,y[10], CC,y[11]);
        o[11] = m4(CC,y[4], CC,y[10],CC,y[11], CC,y[12]);
        o[12] = m4(CC,y[5], CC,y[11],CC,y[12], CB,y[13]);
        o[13] = m3(CA,y[6], CB,y[12],CA,y[13]);
        #pragma unroll
        for (int i = 0; i < 14; ++i) {
            p[i * HSW] = __floats2half2_rn(fmaxf(o[i].x + bias.x, 0.f),
                                           fmaxf(o[i].y + bias.y, 0.f));
        }
    }
    __syncthreads();

    // ---------------- GEMM2: Z[128,64] = H * W2T^T, K=128 ----------------
    float acc2[2][4][4];
    #pragma unroll
    for (int mt = 0; mt < 2; ++mt)
        #pragma unroll
        for (int nt = 0; nt < 4; ++nt)
            #pragma unroll
            for (int r = 0; r < 4; ++r) acc2[mt][nt][r] = 0.f;

    #pragma unroll
    for (int s = 0; s < 8; ++s) {
        uint32_t a[2][4];
        #pragma unroll
        for (int mt = 0; mt < 2; ++mt) {
            const uint32_t* ap = YHw + (wm * 32 + mt * 16 + g) * HSW + s * 8 + t;
            a[mt][0] = ap[0];
            a[mt][1] = ap[8 * HSW];
            a[mt][2] = ap[4];
            a[mt][3] = ap[8 * HSW + 4];
        }
        const uint32_t* bp0 = W2w + (wn * 32 + g) * W2SW + s * 8 + t;
        #pragma unroll
        for (int nt = 0; nt < 4; ++nt) {
            const uint32_t* bp = bp0 + nt * 8 * W2SW;
            uint32_t b0 = bp[0], b1v = bp[4];
            mma16816(acc2[0][nt], a[0][0], a[0][1], a[0][2], a[0][3], b0, b1v);
            mma16816(acc2[1][nt], a[1][0], a[1][1], a[1][2], a[1][3], b0, b1v);
        }
    }
    __syncthreads();   // all YH reads done before Z overwrites the region

    // ---------------- Z -> smem (f32) ----------------
    #pragma unroll
    for (int mt = 0; mt < 2; ++mt) {
        int r0 = wm * 32 + mt * 16 + g;
        float* z0 = Zf + r0 * ZSF + wn * 32 + 2 * t;
        float* z1 = z0 + 8 * ZSF;
        #pragma unroll
        for (int nt = 0; nt < 4; ++nt) {
            *(float2*)(z0 + nt * 8) = make_float2(acc2[mt][nt][0], acc2[mt][nt][1]);
            *(float2*)(z1 + nt * 8) = make_float2(acc2[mt][nt][2], acc2[mt][nt][3]);
        }
    }
    __syncthreads();

    // ---------------- A_hat pass 2 (+b2) -> global ----------------
    float* gout = out + (size_t)blk * ROWS * 64;
    #pragma unroll
    for (int task = tid; task < BPB * 64; task += THREADS) {
        int b = task >> 6, col = task & 63;
        const float* zp = Zf + b * 14 * ZSF + col;
        float z[14], o[14];
        #pragma unroll
        for (int i = 0; i < 14; ++i) z[i] = zp[i * ZSF];
        ahat14(z, o);
        float bv = b2s[col];
        float* gp = gout + (b * 14) * 64 + col;
        #pragma unroll
        for (int i = 0; i < 14; ++i) gp[i * 64] = o[i] + bv;
    }
}

extern "C" void kernel_launch(void* const* d_in, const int* in_sizes, int n_in,
                              void* d_out, int out_size) {
    const float* fea = (const float*)d_in[0];
    const float* W1  = (const float*)d_in[1];
    const float* b1  = (const float*)d_in[2];
    const float* W2  = (const float*)d_in[3];
    const float* b2  = (const float*)d_in[4];
    float* out = (float*)d_out;

    int B = in_sizes[0] / (14 * 256);   // 16384
    int blocks = B / BPB;               // 2048

    prep_kernel<<<160, 256>>>(W1, W2);
    cudaFuncSetAttribute(gcn_occ2_kernel,
                         cudaFuncAttributeMaxDynamicSharedMemorySize, SMEM_BYTES);
    gcn_occ2_kernel<<<blocks, THREADS, SMEM_BYTES>>>(fea, b1, b2, out);
}

// round 14
// speedup vs baseline: 1.2267x; 1.0003x over previous
#include <cuda_runtime.h>
#include <cuda_fp16.h>
#include <cstdint>
#include <cstddef>

// pre-converted fp16 weights, transposed to [n][k]
__device__ __align__(16) __half g_W1h[128 * 256];
__device__ __align__(16) __half g_W2h[64 * 128];

namespace {

constexpr int THREADS = 256;   // 8 warps: 4 M-warps (32 rows) x 2 N-warps (64 cols)
constexpr int BPB     = 8;
constexpr int ROWS    = 112;   // real rows; M padded to 128
constexpr int MPAD    = 128;

constexpr int XSW  = 20;   // X fp16 chunk stride (words)
constexpr int WSW  = 20;   // W1 fp16 chunk stride
constexpr int HSW  = 68;   // Y/H fp16 stride (words)
constexpr int W2SW = 68;   // W2T fp16 stride
constexpr int ZSF  = 72;   // Z f32 stride (floats)

constexpr int XBUFW = MPAD * XSW;   // 2560 words per X buffer
constexpr int WBUFW = 128 * WSW;    // 2560 words per W1 buffer

// byte offsets; union region holds {X staging | YH fp16 | Z f32}
constexpr int O_BIAS = 0;                       // b1(512B)+b2(256B)
constexpr int O_X    = 1024;                    // 3 X buffers: 30720
constexpr int O_W1   = O_X + 3 * XBUFW * 4;     // 31744: 3 W1 buffers: 30720
constexpr int O_W2   = O_W1 + 3 * WBUFW * 4;    // 62464: W2 17408
constexpr int SMEM_BYTES = O_W2 + 64 * W2SW * 4;  // 79872
// YH fp16 (34816 B) and Z f32 (36864 B) alias the staging region at O_X.

__device__ __forceinline__ uint32_t packh2(float a, float b) {
    __half2 h = __floats2half2_rn(a, b);
    return *reinterpret_cast<uint32_t*>(&h);
}

__device__ __forceinline__ void mma16816(float* d,
                                         uint32_t a0, uint32_t a1, uint32_t a2, uint32_t a3,
                                         uint32_t b0, uint32_t b1) {
    asm volatile(
        "mma.sync.aligned.m16n8k16.row.col.f32.f16.f16.f32 "
        "{%0,%1,%2,%3},{%4,%5,%6,%7},{%8,%9},{%0,%1,%2,%3};\n"
        : "+f"(d[0]), "+f"(d[1]), "+f"(d[2]), "+f"(d[3])
        : "r"(a0), "r"(a1), "r"(a2), "r"(a3), "r"(b0), "r"(b1));
}

__device__ __forceinline__ void cp16(uint32_t dst_smem, const void* src) {
    asm volatile("cp.async.cg.shared.global [%0], [%1], 16;\n"
                 :: "r"(dst_smem), "l"(src));
}
__device__ __forceinline__ void cp_commit() {
    asm volatile("cp.async.commit_group;\n" ::: "memory");
}
__device__ __forceinline__ void cp_wait0() {
    asm volatile("cp.async.wait_group 0;\n" ::: "memory");
}
__device__ __forceinline__ void cp_wait1() {
    asm volatile("cp.async.wait_group 1;\n" ::: "memory");
}

// A_hat: degrees (with self-loop) = 3 at teeth {0,6,7,13}, else 4
constexpr float CA = 0.3333333333333333f;
constexpr float CB = 0.28867513459481287f;
constexpr float CC = 0.25f;

__device__ __forceinline__ float2 m3(float wa, float2 a, float wb, float2 b,
                                     float wc, float2 c) {
    return make_float2(wa * a.x + wb * b.x + wc * c.x,
                       wa * a.y + wb * b.y + wc * c.y);
}
__device__ __forceinline__ float2 m4(float wa, float2 a, float wb, float2 b,
                                     float wc, float2 c, float wd, float2 d) {
    return make_float2(wa * a.x + wb * b.x + wc * c.x + wd * d.x,
                       wa * a.y + wb * b.y + wc * c.y + wd * d.y);
}

__device__ __forceinline__ void ahat14(const float* y, float* o) {
    o[0]  = CA*y[0] + CB*y[1] + CA*y[7];
    o[1]  = CB*y[0] + CC*y[1] + CC*y[2]  + CC*y[8];
    o[2]  = CC*y[1] + CC*y[2] + CC*y[3]  + CC*y[9];
    o[3]  = CC*y[2] + CC*y[3] + CC*y[4]  + CC*y[10];
    o[4]  = CC*y[3] + CC*y[4] + CC*y[5]  + CC*y[11];
    o[5]  = CC*y[4] + CC*y[5] + CB*y[6]  + CC*y[12];
    o[6]  = CB*y[5] + CA*y[6] + CA*y[13];
    o[7]  = CA*y[0] + CA*y[7] + CB*y[8];
    o[8]  = CC*y[1] + CB*y[7] + CC*y[8]  + CC*y[9];
    o[9]  = CC*y[2] + CC*y[8] + CC*y[9]  + CC*y[10];
    o[10] = CC*y[3] + CC*y[9] + CC*y[10] + CC*y[11];
    o[11] = CC*y[4] + CC*y[10]+ CC*y[11] + CC*y[12];
    o[12] = CC*y[5] + CC*y[11]+ CC*y[12] + CB*y[13];
    o[13] = CA*y[6] + CB*y[12]+ CA*y[13];
}

} // namespace

__global__ void prep_kernel(const float* __restrict__ W1, const float* __restrict__ W2) {
    int t = blockIdx.x * 256 + threadIdx.x;
    if (t < 32768) {
        int n = t >> 8, k = t & 255;
        g_W1h[n * 256 + k] = __float2half_rn(W1[k * 128 + n]);
    } else if (t < 40960) {
        int u = t - 32768;
        int n = u >> 7, k = u & 127;
        g_W2h[n * 128 + k] = __float2half_rn(W2[k * 64 + n]);
    }
}

__global__ void __launch_bounds__(THREADS, 2)
gcn_pipe_kernel(const float* __restrict__ fea,
                const float* __restrict__ b1,
                const float* __restrict__ b2,
                float* __restrict__ out)
{
    extern __shared__ char sm[];
    const uint32_t smb = (uint32_t)__cvta_generic_to_shared(sm);

    float*    b1s = (float*)(sm + O_BIAS);
    float*    b2s = (float*)(sm + O_BIAS + 512);
    uint32_t* Xw  = (uint32_t*)(sm + O_X);
    uint32_t* W1w = (uint32_t*)(sm + O_W1);
    uint32_t* YHw = (uint32_t*)(sm + O_X);     // [128][68w] fp16, aliases staging
    float*    Zf  = (float*)(sm + O_X);        // [128][72]  f32,  aliases staging
    uint32_t* W2w = (uint32_t*)(sm + O_W2);

    const int tid  = threadIdx.x;
    const int warp = tid >> 5;
    const int lane = tid & 31;
    const int g    = lane >> 2;
    const int t    = lane & 3;
    const int wm   = warp >> 1;   // 0..3: 32-row M tile
    const int wn   = warp & 1;    // 0..1: 64-col N tile
    const int blk  = blockIdx.x;

    const float* feaB = fea + (size_t)blk * ROWS * 256;

    // X staging map: 448 uint4 per chunk (112 rows x 4 segs), <=2 per thread
    const int xrow0 = tid >> 2, xseg0 = tid & 3;         // idx = tid (always < 448)
    const int idx1  = tid + 256;
    const int xrow1 = idx1 >> 2, xseg1 = idx1 & 3;
    const bool has1 = idx1 < 448;

    // ---------------- prologue ----------------
    if (tid < 128) b1s[tid] = b1[tid];
    else if (tid < 192) b2s[tid - 128] = b2[tid - 128];

    // zero pad rows 112..127 of ALL THREE X buffers
    for (int i = tid; i < 3 * 16 * XSW; i += THREADS) {
        int buf = i / (16 * XSW), r = (i / XSW) % 16, w = i % XSW;
        Xw[buf * XBUFW + (112 + r) * XSW + w] = 0u;
    }

    // group0: W2T (1024 x 16B) + W1 chunk0 (512 x 16B)
    for (int i = tid; i < 1024; i += THREADS) {
        int n = i >> 4, seg = i & 15;
        cp16(smb + O_W2 + (uint32_t)(n * W2SW + seg * 4) * 4,
             g_W2h + n * 128 + seg * 8);
    }
    #pragma unroll
    for (int j = 0; j < 2; ++j) {
        int i = tid + j * THREADS;
        int n = i >> 2, seg = i & 3;
        cp16(smb + O_W1 + (uint32_t)(n * WSW + seg * 4) * 4,
             g_W1h + n * 256 + seg * 8);
    }
    cp_commit();
    // group1: W1 chunk1 -> Wbuf1
    #pragma unroll
    for (int j = 0; j < 2; ++j) {
        int i = tid + j * THREADS;
        int n = i >> 2, seg = i & 3;
        cp16(smb + O_W1 + (uint32_t)(WBUFW + n * WSW + seg * 4) * 4,
             g_W1h + n * 256 + 32 + seg * 8);
    }
    cp_commit();

    // X chunk 0 -> Xbuf0 (load + pack + store, one-time exposed latency)
    float4 xf[4];
    {
        const float* xp = feaB + xrow0 * 256 + xseg0 * 8;
        xf[0] = *(const float4*)xp;
        xf[1] = *(const float4*)(xp + 4);
        if (has1) {
            const float* xq2 = feaB + xrow1 * 256 + xseg1 * 8;
            xf[2] = *(const float4*)xq2;
            xf[3] = *(const float4*)(xq2 + 4);
        }
        *(uint4*)(Xw + xrow0 * XSW + xseg0 * 4) =
            make_uint4(packh2(xf[0].x, xf[0].y), packh2(xf[0].z, xf[0].w),
                       packh2(xf[1].x, xf[1].y), packh2(xf[1].z, xf[1].w));
        if (has1)
            *(uint4*)(Xw + xrow1 * XSW + xseg1 * 4) =
                make_uint4(packh2(xf[2].x, xf[2].y), packh2(xf[2].z, xf[2].w),
                           packh2(xf[3].x, xf[3].y), packh2(xf[3].z, xf[3].w));
    }
    // X chunk 1 -> float regs (held; packed+stored at top of iter 0)
    {
        const float* xp = feaB + xrow0 * 256 + 32 + xseg0 * 8;
        xf[0] = *(const float4*)xp;
        xf[1] = *(const float4*)(xp + 4);
        if (has1) {
            const float* xq2 = feaB + xrow1 * 256 + 32 + xseg1 * 8;
            xf[2] = *(const float4*)xq2;
            xf[3] = *(const float4*)(xq2 + 4);
        }
    }
    cp_wait1();          // group0 (W2T + W1 chunk0) complete; group1 pending
    __syncthreads();

    // ---------------- GEMM1: Y[128,128] = Xpad * W1T^T, K=256 ----------------
    float acc1[2][8][4];
    #pragma unroll
    for (int mt = 0; mt < 2; ++mt)
        #pragma unroll
        for (int nt = 0; nt < 8; ++nt)
            #pragma unroll
            for (int r = 0; r < 4; ++r) acc1[mt][nt][r] = 0.f;

    #pragma unroll 1
    for (int c = 0; c < 8; ++c) {
        const int r3 = c % 3;          // buffer being consumed
        const int w3 = (c + 1) % 3;    // X STS target (chunk c+1, regs from last iter)
        const int v3 = (c + 2) % 3;    // W cp.async target (chunk c+2)

        // 1. pack + store chunk c+1 (floats loaded one full iteration ago)
        if (c + 1 < 8) {
            uint32_t* xw = Xw + w3 * XBUFW;
            *(uint4*)(xw + xrow0 * XSW + xseg0 * 4) =
                make_uint4(packh2(xf[0].x, xf[0].y), packh2(xf[0].z, xf[0].w),
                           packh2(xf[1].x, xf[1].y), packh2(xf[1].z, xf[1].w));
            if (has1)
                *(uint4*)(xw + xrow1 * XSW + xseg1 * 4) =
                    make_uint4(packh2(xf[2].x, xf[2].y), packh2(xf[2].z, xf[2].w),
                               packh2(xf[3].x, xf[3].y), packh2(xf[3].z, xf[3].w));
        }
        // 2. issue LDG for chunk c+2 (consumed next iteration) + W1 cp.async
        if (c + 2 < 8) {
            int k0 = (c + 2) * 32;
            const float* xp = feaB + xrow0 * 256 + k0 + xseg0 * 8;
            xf[0] = *(const float4*)xp;
            xf[1] = *(const float4*)(xp + 4);
            if (has1) {
                const float* xq2 = feaB + xrow1 * 256 + k0 + xseg1 * 8;
                xf[2] = *(const float4*)xq2;
                xf[3] = *(const float4*)(xq2 + 4);
            }
            uint32_t wdst = smb + O_W1 + (uint32_t)(v3 * WBUFW) * 4;
            #pragma unroll
            for (int j = 0; j < 2; ++j) {
                int i = tid + j * THREADS;
                int n = i >> 2, seg = i & 3;
                cp16(wdst + (uint32_t)(n * WSW + seg * 4) * 4,
                     g_W1h + n * 256 + k0 + seg * 8);
            }
            cp_commit();
        }

        // 3. mma on chunk c
        const uint32_t* xb = Xw + r3 * XBUFW;
        const uint32_t* wb = W1w + r3 * WBUFW;
        #pragma unroll
        for (int s = 0; s < 2; ++s) {
            uint32_t a[2][4];
            #pragma unroll
            for (int mt = 0; mt < 2; ++mt) {
                const uint32_t* ap = xb + (wm * 32 + mt * 16 + g) * XSW + s * 8 + t;
                a[mt][0] = ap[0];
                a[mt][1] = ap[8 * XSW];
                a[mt][2] = ap[4];
                a[mt][3] = ap[8 * XSW + 4];
            }
            const uint32_t* bp0 = wb + (wn * 64 + g) * WSW + s * 8 + t;
            #pragma unroll
            for (int nt = 0; nt < 8; ++nt) {
                const uint32_t* bp = bp0 + nt * 8 * WSW;
                uint32_t b0 = bp[0], b1v = bp[4];
                mma16816(acc1[0][nt], a[0][0], a[0][1], a[0][2], a[0][3], b0, b1v);
                mma16816(acc1[1][nt], a[1][0], a[1][1], a[1][2], a[1][3], b0, b1v);
            }
        }

        // 4. ensure W(c+1) has landed; then block-wide handoff
        if (c < 6) cp_wait1(); else cp_wait0();
        __syncthreads();
    }

    // ---------------- Y -> YH (fp16, aliases staging; GEMM1 done+synced) ----------------
    #pragma unroll
    for (int mt = 0; mt < 2; ++mt) {
        int r0 = wm * 32 + mt * 16 + g;
        __half2* h0 = (__half2*)YHw + r0 * HSW + wn * 32 + t;
        __half2* h1 = h0 + 8 * HSW;
        #pragma unroll
        for (int nt = 0; nt < 8; ++nt) {
            h0[nt * 4] = __floats2half2_rn(acc1[mt][nt][0], acc1[mt][nt][1]);
            h1[nt * 4] = __floats2half2_rn(acc1[mt][nt][2], acc1[mt][nt][3]);
        }
    }
    __syncthreads();

    // ---------------- A_hat pass 1 (+b1, relu), in place on fp16 YH ----------------
    const float2* b1s2 = (const float2*)b1s;
    #pragma unroll
    for (int task = tid; task < BPB * 64; task += THREADS) {
        int b = task >> 6, cw = task & 63;
        __half2* p = (__half2*)YHw + (b * 14) * HSW + cw;
        float2 y[14];
        #pragma unroll
        for (int i = 0; i < 14; ++i) y[i] = __half22float2(p[i * HSW]);
        float2 bias = b1s2[cw];
        float2 o[14];
        o[0]  = m3(CA,y[0], CB,y[1], CA,y[7]);
        o[1]  = m4(CB,y[0], CC,y[1], CC,y[2],  CC,y[8]);
        o[2]  = m4(CC,y[1], CC,y[2], CC,y[3],  CC,y[9]);
        o[3]  = m4(CC,y[2], CC,y[3], CC,y[4],  CC,y[10]);
        o[4]  = m4(CC,y[3], CC,y[4], CC,y[5],  CC,y[11]);
        o[5]  = m4(CC,y[4], CC,y[5], CB,y[6],  CC,y[12]);
        o[6]  = m3(CB,y[5], CA,y[6], CA,y[13]);
        o[7]  = m3(CA,y[0], CA,y[7], CB,y[8]);
        o[8]  = m4(CC,y[1], CB,y[7], CC,y[8],  CC,y[9]);
        o[9]  = m4(CC,y[2], CC,y[8], CC,y[9],  CC,y[10]);
        o[10] = m4(CC,y[3], CC,y[9], CC,y[10], CC,y[11]);
        o[11] = m4(CC,y[4], CC,y[10],CC,y[11], CC,y[12]);
        o[12] = m4(CC,y[5], CC,y[11],CC,y[12], CB,y[13]);
        o[13] = m3(CA,y[6], CB,y[12],CA,y[13]);
        #pragma unroll
        for (int i = 0; i < 14; ++i) {
            p[i * HSW] = __floats2half2_rn(fmaxf(o[i].x + bias.x, 0.f),
                                           fmaxf(o[i].y + bias.y, 0.f));
        }
    }
    __syncthreads();

    // ---------------- GEMM2: Z[128,64] = H * W2T^T, K=128 ----------------
    float acc2[2][4][4];
    #pragma unroll
    for (int mt = 0; mt < 2; ++mt)
        #pragma unroll
        for (int nt = 0; nt < 4; ++nt)
            #pragma unroll
            for (int r = 0; r < 4; ++r) acc2[mt][nt][r] = 0.f;

    #pragma unroll
    for (int s = 0; s < 8; ++s) {
        uint32_t a[2][4];
        #pragma unroll
        for (int mt = 0; mt < 2; ++mt) {
            const uint32_t* ap = YHw + (wm * 32 + mt * 16 + g) * HSW + s * 8 + t;
            a[mt][0] = ap[0];
            a[mt][1] = ap[8 * HSW];
            a[mt][2] = ap[4];
            a[mt][3] = ap[8 * HSW + 4];
        }
        const uint32_t* bp0 = W2w + (wn * 32 + g) * W2SW + s * 8 + t;
        #pragma unroll
        for (int nt = 0; nt < 4; ++nt) {
            const uint32_t* bp = bp0 + nt * 8 * W2SW;
            uint32_t b0 = bp[0], b1v = bp[4];
            mma16816(acc2[0][nt], a[0][0], a[0][1], a[0][2], a[0][3], b0, b1v);
            mma16816(acc2[1][nt], a[1][0], a[1][1], a[1][2], a[1][3], b0, b1v);
        }
    }
    __syncthreads();   // all YH reads done before Z overwrites the region

    // ---------------- Z -> smem (f32) ----------------
    #pragma unroll
    for (int mt = 0; mt < 2; ++mt) {
        int r0 = wm * 32 + mt * 16 + g;
        float* z0 = Zf + r0 * ZSF + wn * 32 + 2 * t;
        float* z1 = z0 + 8 * ZSF;
        #pragma unroll
        for (int nt = 0; nt < 4; ++nt) {
            *(float2*)(z0 + nt * 8) = make_float2(acc2[mt][nt][0], acc2[mt][nt][1]);
            *(float2*)(z1 + nt * 8) = make_float2(acc2[mt][nt][2], acc2[mt][nt][3]);
        }
    }
    __syncthreads();

    // ---------------- A_hat pass 2 (+b2) -> global ----------------
    float* gout = out + (size_t)blk * ROWS * 64;
    #pragma unroll
    for (int task = tid; task < BPB * 64; task += THREADS) {
        int b = task >> 6, col = task & 63;
        const float* zp = Zf + b * 14 * ZSF + col;
        float z[14], o[14];
        #pragma unroll
        for (int i = 0; i < 14; ++i) z[i] = zp[i * ZSF];
        ahat14(z, o);
        float bv = b2s[col];
        float* gp = gout + (b * 14) * 64 + col;
        #pragma unroll
        for (int i = 0; i < 14; ++i) gp[i * 64] = o[i] + bv;
    }
}

extern "C" void kernel_launch(void* const* d_in, const int* in_sizes, int n_in,
                              void* d_out, int out_size) {
    const float* fea = (const float*)d_in[0];
    const float* W1  = (const float*)d_in[1];
    const float* b1  = (const float*)d_in[2];
    const float* W2  = (const float*)d_in[3];
    const float* b2  = (const float*)d_in[4];
    float* out = (float*)d_out;

    int B = in_sizes[0] / (14 * 256);   // 16384
    int blocks = B / BPB;               // 2048

    prep_kernel<<<160, 256>>>(W1, W2);
    cudaFuncSetAttribute(gcn_pipe_kernel,
                         cudaFuncAttributeMaxDynamicSharedMemorySize, SMEM_BYTES);
    gcn_pipe_kernel<<<blocks, THREADS, SMEM_BYTES>>>(fea, b1, b2, out);
}